// round 4
// baseline (speedup 1.0000x reference)
#include <cuda_runtime.h>

#define NB 8
#define NN 512
#define DD 256
#define DH 64
#define NROWS (NB*NN)   // 4096

#define ATTN_BLOCKS 256          // 16 q-rows per block
#define COPY_BLOCKS 188          // 256+188 = 444 = 3 CTAs/SM * 148 SMs
#define GRID_TOTAL (ATTN_BLOCKS + COPY_BLOCKS)

// smem: Qs 16*64 + KsT 64*128 + S 16*512 + Mj 512 = 17920 floats = 71680 B
#define SMEM_BYTES (17920 * 4)

__device__ float g_Q[NROWS*DH];
__device__ float g_K[NROWS*DH];
__device__ float g_V[NROWS*DH];

// ---------------------------------------------------------------------------
// QKV projection: X(4096x256) @ {Wq,Wk,Wv}(256x64) + bias, masked rows.
// ---------------------------------------------------------------------------
__global__ __launch_bounds__(256) void qkv_kernel(
    const float* __restrict__ x, const int* __restrict__ mask,
    const float* __restrict__ Wq, const float* __restrict__ bq,
    const float* __restrict__ Wk, const float* __restrict__ bk,
    const float* __restrict__ Wv, const float* __restrict__ bv)
{
    __shared__ float xs[32*DD];
    const int row0 = blockIdx.x * 32;
    const int t = threadIdx.x;

    const float4* x4 = reinterpret_cast<const float4*>(x + (size_t)row0 * DD);
    float4* xs4 = reinterpret_cast<float4*>(xs);
    #pragma unroll
    for (int i = t; i < 32*DD/4; i += 256) xs4[i] = x4[i];
    __syncthreads();

    const int tx = t & 63;
    const int ty = t >> 6;

    float accq[8], acck[8], accv[8];
    #pragma unroll
    for (int r = 0; r < 8; r++) { accq[r] = 0.f; acck[r] = 0.f; accv[r] = 0.f; }

    for (int k = 0; k < DD; k += 4) {
        float4 xv4[8];
        #pragma unroll
        for (int r = 0; r < 8; r++)
            xv4[r] = *reinterpret_cast<const float4*>(&xs[(ty + r*4)*DD + k]);
        #pragma unroll
        for (int kk = 0; kk < 4; kk++) {
            float wq = Wq[(k+kk)*DH + tx];
            float wk = Wk[(k+kk)*DH + tx];
            float wv = Wv[(k+kk)*DH + tx];
            #pragma unroll
            for (int r = 0; r < 8; r++) {
                float xv = reinterpret_cast<const float*>(&xv4[r])[kk];
                accq[r] = fmaf(xv, wq, accq[r]);
                acck[r] = fmaf(xv, wk, acck[r]);
                accv[r] = fmaf(xv, wv, accv[r]);
            }
        }
    }

    const float bqv = bq[tx], bkv = bk[tx], bvv = bv[tx];
    #pragma unroll
    for (int r = 0; r < 8; r++) {
        int row = row0 + ty + r*4;
        float m = (float)mask[row];
        g_Q[row*DH + tx] = (accq[r] + bqv) * m;
        g_K[row*DH + tx] = (acck[r] + bkv) * m;
        g_V[row*DH + tx] = (accv[r] + bvv) * m;
    }
}

// ---------------------------------------------------------------------------
// Fused: blocks [0,256) = attention (16 q-rows each), blocks [256,444) = the
// 256 MB "e" passthrough copy. Attention uses ~0% DRAM so the copy overlaps.
// ---------------------------------------------------------------------------
__global__ __launch_bounds__(256) void fused_kernel(
    const int* __restrict__ mask, float* __restrict__ out,
    const float* __restrict__ e)
{
    const int t = threadIdx.x;

    if (blockIdx.x >= ATTN_BLOCKS) {
        // -------- copy section: e -> out + NROWS*DH, 16.7M float4 --------
        const float4* __restrict__ src = reinterpret_cast<const float4*>(e);
        float4* __restrict__ dst = reinterpret_cast<float4*>(out + (size_t)NROWS*DH);
        const size_t n4 = (size_t)NB*NN*NN*32/4;               // 16777216
        const size_t stride = (size_t)COPY_BLOCKS*256;
        size_t base = (size_t)(blockIdx.x - ATTN_BLOCKS)*256 + t;
        for (size_t i = base; i < n4; i += stride*8) {
            float4 r[8];
            #pragma unroll
            for (int u = 0; u < 8; u++) {
                size_t p = i + (size_t)u*stride;
                if (p < n4) r[u] = src[p];
            }
            #pragma unroll
            for (int u = 0; u < 8; u++) {
                size_t p = i + (size_t)u*stride;
                if (p < n4) dst[p] = r[u];
            }
        }
        return;
    }

    // -------- attention section --------
    extern __shared__ float sm[];
    float* Qs  = sm;                  // 1024 floats (16 x 64)
    float* KsT = sm + 1024;           // 8192 floats (64 k x 128 j)
    float* S   = sm + 9216;           // 8192 floats (16 x 512)
    float* Mj  = sm + 17408;          // 512

    const int b  = blockIdx.x >> 5;          // 32 blocks per batch
    const int i0 = (blockIdx.x & 31) * 16;

    for (int j = t; j < NN; j += 256) Mj[j] = (float)mask[b*NN + j];
    {
        const float4* q4 = reinterpret_cast<const float4*>(g_Q + (size_t)(b*NN + i0)*DH);
        reinterpret_cast<float4*>(Qs)[t] = q4[t];     // 256 float4 = 16x64
    }
    __syncthreads();

    const int tx = t & 31;            // j group (4 consecutive j each)
    const int ty = t >> 5;            // 0..7 ; rows ty and ty+8
    float4* Qs4  = reinterpret_cast<float4*>(Qs);
    float4* KsT4 = reinterpret_cast<float4*>(KsT);
    float4* S4   = reinterpret_cast<float4*>(S);

    for (int jt = 0; jt < 4; jt++) {
        const int j0 = jt * 128;

        // load K tile transposed: KsT[k][j]
        {
            const int j    = t & 127;
            const int half = t >> 7;
            const float4* K4 = reinterpret_cast<const float4*>(g_K) +
                               (size_t)(b*NN + j0 + j) * 16;
            #pragma unroll
            for (int i2 = 0; i2 < 8; i2++) {
                int k4 = half*8 + i2;
                float4 v = K4[k4];
                KsT[(k4*4+0)*128 + j] = v.x;
                KsT[(k4*4+1)*128 + j] = v.y;
                KsT[(k4*4+2)*128 + j] = v.z;
                KsT[(k4*4+3)*128 + j] = v.w;
            }
        }
        __syncthreads();

        float acc[2][4];
        #pragma unroll
        for (int c = 0; c < 2; c++)
            #pragma unroll
            for (int a = 0; a < 4; a++) acc[c][a] = 0.f;

        #pragma unroll 4
        for (int k4 = 0; k4 < 16; k4++) {
            float4 q0 = Qs4[ ty     *16 + k4];
            float4 q1 = Qs4[(ty+8)*16 + k4];
            #pragma unroll
            for (int kk = 0; kk < 4; kk++) {
                float4 kv = KsT4[(k4*4 + kk)*32 + tx];
                float qa = reinterpret_cast<const float*>(&q0)[kk];
                float qb = reinterpret_cast<const float*>(&q1)[kk];
                acc[0][0] = fmaf(qa, kv.x, acc[0][0]);
                acc[0][1] = fmaf(qa, kv.y, acc[0][1]);
                acc[0][2] = fmaf(qa, kv.z, acc[0][2]);
                acc[0][3] = fmaf(qa, kv.w, acc[0][3]);
                acc[1][0] = fmaf(qb, kv.x, acc[1][0]);
                acc[1][1] = fmaf(qb, kv.y, acc[1][1]);
                acc[1][2] = fmaf(qb, kv.z, acc[1][2]);
                acc[1][3] = fmaf(qb, kv.w, acc[1][3]);
            }
        }

        {
            const float mi0 = Mj[i0 + ty];
            const float mi1 = Mj[i0 + ty + 8];
            const int jb = j0 + tx*4;
            float4 s0, s1;
            s0.x = (mi0*Mj[jb+0] != 0.f) ? acc[0][0]*0.125f : -1.0e9f;
            s0.y = (mi0*Mj[jb+1] != 0.f) ? acc[0][1]*0.125f : -1.0e9f;
            s0.z = (mi0*Mj[jb+2] != 0.f) ? acc[0][2]*0.125f : -1.0e9f;
            s0.w = (mi0*Mj[jb+3] != 0.f) ? acc[0][3]*0.125f : -1.0e9f;
            s1.x = (mi1*Mj[jb+0] != 0.f) ? acc[1][0]*0.125f : -1.0e9f;
            s1.y = (mi1*Mj[jb+1] != 0.f) ? acc[1][1]*0.125f : -1.0e9f;
            s1.z = (mi1*Mj[jb+2] != 0.f) ? acc[1][2]*0.125f : -1.0e9f;
            s1.w = (mi1*Mj[jb+3] != 0.f) ? acc[1][3]*0.125f : -1.0e9f;
            S4[ ty    *128 + (jb>>2)] = s0;
            S4[(ty+8)*128 + (jb>>2)] = s1;
        }
        __syncthreads();
    }

    // ---- softmax: warp per row pair ----
    {
        const int warp = t >> 5, lane = t & 31;
        #pragma unroll
        for (int rr = 0; rr < 2; rr++) {
            int row = warp*2 + rr;
            float vals[16];
            float mx = -3.4e38f;
            #pragma unroll
            for (int m = 0; m < 16; m++) {
                vals[m] = S[row*NN + lane + 32*m];
                mx = fmaxf(mx, vals[m]);
            }
            #pragma unroll
            for (int o = 16; o > 0; o >>= 1)
                mx = fmaxf(mx, __shfl_xor_sync(0xffffffffu, mx, o));
            float sum = 0.f;
            #pragma unroll
            for (int m = 0; m < 16; m++) { vals[m] = __expf(vals[m] - mx); sum += vals[m]; }
            #pragma unroll
            for (int o = 16; o > 0; o >>= 1)
                sum += __shfl_xor_sync(0xffffffffu, sum, o);
            float inv = 1.f / sum;
            #pragma unroll
            for (int m = 0; m < 16; m++) S[row*NN + lane + 32*m] = vals[m]*inv;
        }
    }
    __syncthreads();

    // ---- out = P @ V (one row per thread, float4 over dd) ----
    {
        const int ty4 = t >> 4;       // row 0..15
        const int tx4 = t & 15;       // dd group
        float4 acc = {0.f, 0.f, 0.f, 0.f};
        const float4* __restrict__ V4 =
            reinterpret_cast<const float4*>(g_V) + (size_t)b*NN*16;
        #pragma unroll 2
        for (int j4 = 0; j4 < 128; j4++) {
            float4 s  = S4[ty4*128 + j4];
            float4 v0 = V4[(j4*4+0)*16 + tx4];
            float4 v1 = V4[(j4*4+1)*16 + tx4];
            float4 v2 = V4[(j4*4+2)*16 + tx4];
            float4 v3 = V4[(j4*4+3)*16 + tx4];
            acc.x = fmaf(s.x, v0.x, acc.x); acc.y = fmaf(s.x, v0.y, acc.y);
            acc.z = fmaf(s.x, v0.z, acc.z); acc.w = fmaf(s.x, v0.w, acc.w);
            acc.x = fmaf(s.y, v1.x, acc.x); acc.y = fmaf(s.y, v1.y, acc.y);
            acc.z = fmaf(s.y, v1.z, acc.z); acc.w = fmaf(s.y, v1.w, acc.w);
            acc.x = fmaf(s.z, v2.x, acc.x); acc.y = fmaf(s.z, v2.y, acc.y);
            acc.z = fmaf(s.z, v2.z, acc.z); acc.w = fmaf(s.z, v2.w, acc.w);
            acc.x = fmaf(s.w, v3.x, acc.x); acc.y = fmaf(s.w, v3.y, acc.y);
            acc.z = fmaf(s.w, v3.z, acc.z); acc.w = fmaf(s.w, v3.w, acc.w);
        }
        float m = Mj[i0 + ty4];
        acc.x *= m; acc.y *= m; acc.z *= m; acc.w *= m;
        reinterpret_cast<float4*>(out)[(size_t)(b*NN + i0 + ty4)*16 + tx4] = acc;
    }
}

// ---------------------------------------------------------------------------
extern "C" void kernel_launch(void* const* d_in, const int* in_sizes, int n_in,
                              void* d_out, int out_size)
{
    const float* x  = (const float*)d_in[0];
    const float* e  = (const float*)d_in[1];
    const int*  msk = (const int*)  d_in[2];
    const float* Wq = (const float*)d_in[3];
    const float* bq = (const float*)d_in[4];
    const float* Wk = (const float*)d_in[5];
    const float* bk = (const float*)d_in[6];
    const float* Wv = (const float*)d_in[7];
    const float* bv = (const float*)d_in[8];
    float* out = (float*)d_out;

    qkv_kernel<<<128, 256>>>(x, msk, Wq, bq, Wk, bk, Wv, bv);

    cudaFuncSetAttribute(fused_kernel, cudaFuncAttributeMaxDynamicSharedMemorySize,
                         SMEM_BYTES);
    fused_kernel<<<GRID_TOTAL, 256, SMEM_BYTES>>>(msk, out, e);
}

// round 5
// speedup vs baseline: 1.3268x; 1.3268x over previous
#include <cuda_runtime.h>

#define NB 8
#define NN 512
#define DD 256
#define DH 64
#define NROWS (NB*NN)   // 4096

#define ATTN_BLOCKS 256          // 16 q-rows per block
#define GRID_TOTAL 444           // 3 CTAs/SM * 148 SMs

// e passthrough: 16777216 float4 total, 1024 chunks of 16384 float4
#define COPY_N4   ((size_t)NB*NN*NN*32/4)
#define CHUNK4    16384
#define NCHUNKS   1024

// smem: Qs 16*64 + KsT 64*128 + S 16*512 + Mj 512 = 17920 floats = 71680 B
#define SMEM_BYTES (17920 * 4)

__device__ float g_Q[NROWS*DH];
__device__ float g_K[NROWS*DH];
__device__ float g_V[NROWS*DH];
__device__ int   g_chunk;        // work-stealing counter for the copy

// ---------------------------------------------------------------------------
// QKV projection: X(4096x256) @ {Wq,Wk,Wv}(256x64) + bias, masked rows.
// Also resets the copy chunk counter (runs before fused_kernel in-stream).
// ---------------------------------------------------------------------------
__global__ __launch_bounds__(256) void qkv_kernel(
    const float* __restrict__ x, const int* __restrict__ mask,
    const float* __restrict__ Wq, const float* __restrict__ bq,
    const float* __restrict__ Wk, const float* __restrict__ bk,
    const float* __restrict__ Wv, const float* __restrict__ bv)
{
    if (blockIdx.x == 0 && threadIdx.x == 0) g_chunk = 0;

    __shared__ float xs[32*DD];
    const int row0 = blockIdx.x * 32;
    const int t = threadIdx.x;

    const float4* x4 = reinterpret_cast<const float4*>(x + (size_t)row0 * DD);
    float4* xs4 = reinterpret_cast<float4*>(xs);
    #pragma unroll
    for (int i = t; i < 32*DD/4; i += 256) xs4[i] = x4[i];
    __syncthreads();

    const int tx = t & 63;
    const int ty = t >> 6;

    float accq[8], acck[8], accv[8];
    #pragma unroll
    for (int r = 0; r < 8; r++) { accq[r] = 0.f; acck[r] = 0.f; accv[r] = 0.f; }

    for (int k = 0; k < DD; k += 4) {
        float4 xv4[8];
        #pragma unroll
        for (int r = 0; r < 8; r++)
            xv4[r] = *reinterpret_cast<const float4*>(&xs[(ty + r*4)*DD + k]);
        #pragma unroll
        for (int kk = 0; kk < 4; kk++) {
            float wq = Wq[(k+kk)*DH + tx];
            float wk = Wk[(k+kk)*DH + tx];
            float wv = Wv[(k+kk)*DH + tx];
            #pragma unroll
            for (int r = 0; r < 8; r++) {
                float xv = reinterpret_cast<const float*>(&xv4[r])[kk];
                accq[r] = fmaf(xv, wq, accq[r]);
                acck[r] = fmaf(xv, wk, acck[r]);
                accv[r] = fmaf(xv, wv, accv[r]);
            }
        }
    }

    const float bqv = bq[tx], bkv = bk[tx], bvv = bv[tx];
    #pragma unroll
    for (int r = 0; r < 8; r++) {
        int row = row0 + ty + r*4;
        float m = (float)mask[row];
        g_Q[row*DH + tx] = (accq[r] + bqv) * m;
        g_K[row*DH + tx] = (acck[r] + bkv) * m;
        g_V[row*DH + tx] = (accv[r] + bvv) * m;
    }
}

// ---------------------------------------------------------------------------
// Fused: blocks [0,256) run one attention tile, then ALL blocks work-steal
// copy chunks (e -> out tail). Streaming loads/stores keep L2 for K/V.
// ---------------------------------------------------------------------------
__global__ __launch_bounds__(256) void fused_kernel(
    const int* __restrict__ mask, float* __restrict__ out,
    const float* __restrict__ e)
{
    extern __shared__ float sm[];
    const int t = threadIdx.x;

    if (blockIdx.x < ATTN_BLOCKS) {
        float* Qs  = sm;                  // 1024 floats (16 x 64)
        float* KsT = sm + 1024;           // 8192 floats (64 k x 128 j)
        float* S   = sm + 9216;           // 8192 floats (16 x 512)
        float* Mj  = sm + 17408;          // 512

        const int b  = blockIdx.x >> 5;
        const int i0 = (blockIdx.x & 31) * 16;

        for (int j = t; j < NN; j += 256) Mj[j] = (float)mask[b*NN + j];
        {
            const float4* q4 = reinterpret_cast<const float4*>(g_Q + (size_t)(b*NN + i0)*DH);
            reinterpret_cast<float4*>(Qs)[t] = q4[t];
        }
        __syncthreads();

        const int tx = t & 31;
        const int ty = t >> 5;
        float4* Qs4  = reinterpret_cast<float4*>(Qs);
        float4* KsT4 = reinterpret_cast<float4*>(KsT);
        float4* S4   = reinterpret_cast<float4*>(S);

        for (int jt = 0; jt < 4; jt++) {
            const int j0 = jt * 128;
            {
                const int j    = t & 127;
                const int half = t >> 7;
                const float4* K4 = reinterpret_cast<const float4*>(g_K) +
                                   (size_t)(b*NN + j0 + j) * 16;
                #pragma unroll
                for (int i2 = 0; i2 < 8; i2++) {
                    int k4 = half*8 + i2;
                    float4 v = K4[k4];
                    KsT[(k4*4+0)*128 + j] = v.x;
                    KsT[(k4*4+1)*128 + j] = v.y;
                    KsT[(k4*4+2)*128 + j] = v.z;
                    KsT[(k4*4+3)*128 + j] = v.w;
                }
            }
            __syncthreads();

            float acc[2][4];
            #pragma unroll
            for (int c = 0; c < 2; c++)
                #pragma unroll
                for (int a = 0; a < 4; a++) acc[c][a] = 0.f;

            #pragma unroll 4
            for (int k4 = 0; k4 < 16; k4++) {
                float4 q0 = Qs4[ ty    *16 + k4];
                float4 q1 = Qs4[(ty+8)*16 + k4];
                #pragma unroll
                for (int kk = 0; kk < 4; kk++) {
                    float4 kv = KsT4[(k4*4 + kk)*32 + tx];
                    float qa = reinterpret_cast<const float*>(&q0)[kk];
                    float qb = reinterpret_cast<const float*>(&q1)[kk];
                    acc[0][0] = fmaf(qa, kv.x, acc[0][0]);
                    acc[0][1] = fmaf(qa, kv.y, acc[0][1]);
                    acc[0][2] = fmaf(qa, kv.z, acc[0][2]);
                    acc[0][3] = fmaf(qa, kv.w, acc[0][3]);
                    acc[1][0] = fmaf(qb, kv.x, acc[1][0]);
                    acc[1][1] = fmaf(qb, kv.y, acc[1][1]);
                    acc[1][2] = fmaf(qb, kv.z, acc[1][2]);
                    acc[1][3] = fmaf(qb, kv.w, acc[1][3]);
                }
            }

            {
                const float mi0 = Mj[i0 + ty];
                const float mi1 = Mj[i0 + ty + 8];
                const int jb = j0 + tx*4;
                float4 s0, s1;
                s0.x = (mi0*Mj[jb+0] != 0.f) ? acc[0][0]*0.125f : -1.0e9f;
                s0.y = (mi0*Mj[jb+1] != 0.f) ? acc[0][1]*0.125f : -1.0e9f;
                s0.z = (mi0*Mj[jb+2] != 0.f) ? acc[0][2]*0.125f : -1.0e9f;
                s0.w = (mi0*Mj[jb+3] != 0.f) ? acc[0][3]*0.125f : -1.0e9f;
                s1.x = (mi1*Mj[jb+0] != 0.f) ? acc[1][0]*0.125f : -1.0e9f;
                s1.y = (mi1*Mj[jb+1] != 0.f) ? acc[1][1]*0.125f : -1.0e9f;
                s1.z = (mi1*Mj[jb+2] != 0.f) ? acc[1][2]*0.125f : -1.0e9f;
                s1.w = (mi1*Mj[jb+3] != 0.f) ? acc[1][3]*0.125f : -1.0e9f;
                S4[ ty    *128 + (jb>>2)] = s0;
                S4[(ty+8)*128 + (jb>>2)] = s1;
            }
            __syncthreads();
        }

        // softmax: warp per row pair
        {
            const int warp = t >> 5, lane = t & 31;
            #pragma unroll
            for (int rr = 0; rr < 2; rr++) {
                int row = warp*2 + rr;
                float vals[16];
                float mx = -3.4e38f;
                #pragma unroll
                for (int m = 0; m < 16; m++) {
                    vals[m] = S[row*NN + lane + 32*m];
                    mx = fmaxf(mx, vals[m]);
                }
                #pragma unroll
                for (int o = 16; o > 0; o >>= 1)
                    mx = fmaxf(mx, __shfl_xor_sync(0xffffffffu, mx, o));
                float sum = 0.f;
                #pragma unroll
                for (int m = 0; m < 16; m++) { vals[m] = __expf(vals[m] - mx); sum += vals[m]; }
                #pragma unroll
                for (int o = 16; o > 0; o >>= 1)
                    sum += __shfl_xor_sync(0xffffffffu, sum, o);
                float inv = 1.f / sum;
                #pragma unroll
                for (int m = 0; m < 16; m++) S[row*NN + lane + 32*m] = vals[m]*inv;
            }
        }
        __syncthreads();

        // out = P @ V (one row per thread, float4 over dd)
        {
            const int ty4 = t >> 4;
            const int tx4 = t & 15;
            float4 acc = {0.f, 0.f, 0.f, 0.f};
            const float4* __restrict__ V4 =
                reinterpret_cast<const float4*>(g_V) + (size_t)b*NN*16;
            #pragma unroll 2
            for (int j4 = 0; j4 < 128; j4++) {
                float4 s  = S4[ty4*128 + j4];
                float4 v0 = V4[(j4*4+0)*16 + tx4];
                float4 v1 = V4[(j4*4+1)*16 + tx4];
                float4 v2 = V4[(j4*4+2)*16 + tx4];
                float4 v3 = V4[(j4*4+3)*16 + tx4];
                acc.x = fmaf(s.x, v0.x, acc.x); acc.y = fmaf(s.x, v0.y, acc.y);
                acc.z = fmaf(s.x, v0.z, acc.z); acc.w = fmaf(s.x, v0.w, acc.w);
                acc.x = fmaf(s.y, v1.x, acc.x); acc.y = fmaf(s.y, v1.y, acc.y);
                acc.z = fmaf(s.y, v1.z, acc.z); acc.w = fmaf(s.y, v1.w, acc.w);
                acc.x = fmaf(s.z, v2.x, acc.x); acc.y = fmaf(s.z, v2.y, acc.y);
                acc.z = fmaf(s.z, v2.z, acc.z); acc.w = fmaf(s.z, v2.w, acc.w);
                acc.x = fmaf(s.w, v3.x, acc.x); acc.y = fmaf(s.w, v3.y, acc.y);
                acc.z = fmaf(s.w, v3.z, acc.z); acc.w = fmaf(s.w, v3.w, acc.w);
            }
            float m = Mj[i0 + ty4];
            acc.x *= m; acc.y *= m; acc.z *= m; acc.w *= m;
            reinterpret_cast<float4*>(out)[(size_t)(b*NN + i0 + ty4)*16 + tx4] = acc;
        }
        __syncthreads();   // smem about to be reused as chunk mailbox
    }

    // -------- copy phase: all blocks work-steal 256KB chunks --------
    {
        int* smi = reinterpret_cast<int*>(sm);
        const float4* __restrict__ src = reinterpret_cast<const float4*>(e);
        float4* __restrict__ dst = reinterpret_cast<float4*>(out + (size_t)NROWS*DH);

        for (;;) {
            if (t == 0) smi[0] = atomicAdd(&g_chunk, 1);
            __syncthreads();
            const int c = smi[0];
            if (c >= NCHUNKS) break;

            const size_t base = (size_t)c * CHUNK4 + t;
            #pragma unroll 1
            for (int u = 0; u < CHUNK4/256; u += 8) {     // 64 float4/thread, 8-deep
                float4 r[8];
                #pragma unroll
                for (int v = 0; v < 8; v++)
                    r[v] = __ldcs(&src[base + (size_t)(u+v)*256]);
                #pragma unroll
                for (int v = 0; v < 8; v++)
                    __stcs(&dst[base + (size_t)(u+v)*256], r[v]);
            }
            __syncthreads();
        }
    }
}

// ---------------------------------------------------------------------------
extern "C" void kernel_launch(void* const* d_in, const int* in_sizes, int n_in,
                              void* d_out, int out_size)
{
    const float* x  = (const float*)d_in[0];
    const float* e  = (const float*)d_in[1];
    const int*  msk = (const int*)  d_in[2];
    const float* Wq = (const float*)d_in[3];
    const float* bq = (const float*)d_in[4];
    const float* Wk = (const float*)d_in[5];
    const float* bk = (const float*)d_in[6];
    const float* Wv = (const float*)d_in[7];
    const float* bv = (const float*)d_in[8];
    float* out = (float*)d_out;

    qkv_kernel<<<128, 256>>>(x, msk, Wq, bq, Wk, bk, Wv, bv);

    cudaFuncSetAttribute(fused_kernel, cudaFuncAttributeMaxDynamicSharedMemorySize,
                         SMEM_BYTES);
    fused_kernel<<<GRID_TOTAL, 256, SMEM_BYTES>>>(msk, out, e);
}

// round 7
// speedup vs baseline: 1.3722x; 1.0342x over previous
#include <cuda_runtime.h>

#define NB 8
#define NN 512
#define DD 256
#define DH 64
#define NROWS (NB*NN)   // 4096

#define ATTN_BLOCKS 256          // 16 q-rows per block
#define GRID_TOTAL 444           // 3 CTAs/SM * 148 SMs

// e passthrough: 16777216 float4 total; 32KB chunks stolen per-warp
#define CHUNK4    2048
#define NCHUNKS   8192

// smem: Qs 16*64 + KsT/Vs 64*128 + S 16*512 + Mj 512 = 17920 floats = 71680 B
#define SMEM_BYTES (17920 * 4)

__device__ float g_Q[NROWS*DH];
__device__ float g_K[NROWS*DH];
__device__ float g_V[NROWS*DH];
__device__ int   g_chunk;        // work-stealing counter for the copy

// ---------------------------------------------------------------------------
// QKV projection: X(4096x256) @ {Wq,Wk,Wv}(256x64) + bias, masked rows.
// Also resets the copy chunk counter (runs before fused_kernel in-stream).
// ---------------------------------------------------------------------------
__global__ __launch_bounds__(256) void qkv_kernel(
    const float* __restrict__ x, const int* __restrict__ mask,
    const float* __restrict__ Wq, const float* __restrict__ bq,
    const float* __restrict__ Wk, const float* __restrict__ bk,
    const float* __restrict__ Wv, const float* __restrict__ bv)
{
    if (blockIdx.x == 0 && threadIdx.x == 0) g_chunk = 0;

    __shared__ float xs[32*DD];
    const int row0 = blockIdx.x * 32;
    const int t = threadIdx.x;

    const float4* x4 = reinterpret_cast<const float4*>(x + (size_t)row0 * DD);
    float4* xs4 = reinterpret_cast<float4*>(xs);
    #pragma unroll
    for (int i = t; i < 32*DD/4; i += 256) xs4[i] = x4[i];
    __syncthreads();

    const int tx = t & 63;
    const int ty = t >> 6;

    float accq[8], acck[8], accv[8];
    #pragma unroll
    for (int r = 0; r < 8; r++) { accq[r] = 0.f; acck[r] = 0.f; accv[r] = 0.f; }

    for (int k = 0; k < DD; k += 4) {
        float4 xv4[8];
        #pragma unroll
        for (int r = 0; r < 8; r++)
            xv4[r] = *reinterpret_cast<const float4*>(&xs[(ty + r*4)*DD + k]);
        #pragma unroll
        for (int kk = 0; kk < 4; kk++) {
            float wq = Wq[(k+kk)*DH + tx];
            float wk = Wk[(k+kk)*DH + tx];
            float wv = Wv[(k+kk)*DH + tx];
            #pragma unroll
            for (int r = 0; r < 8; r++) {
                float xv = reinterpret_cast<const float*>(&xv4[r])[kk];
                accq[r] = fmaf(xv, wq, accq[r]);
                acck[r] = fmaf(xv, wk, acck[r]);
                accv[r] = fmaf(xv, wv, accv[r]);
            }
        }
    }

    const float bqv = bq[tx], bkv = bk[tx], bvv = bv[tx];
    #pragma unroll
    for (int r = 0; r < 8; r++) {
        int row = row0 + ty + r*4;
        float m = (float)mask[row];
        g_Q[row*DH + tx] = (accq[r] + bqv) * m;
        g_K[row*DH + tx] = (acck[r] + bkv) * m;
        g_V[row*DH + tx] = (accv[r] + bvv) * m;
    }
}

// ---------------------------------------------------------------------------
// Fused: blocks [0,256) run one attention tile (K and V both staged through
// smem), then ALL warps work-steal 32KB copy chunks (e -> out tail).
// ---------------------------------------------------------------------------
__global__ __launch_bounds__(256) void fused_kernel(
    const int* __restrict__ mask, float* __restrict__ out,
    const float* __restrict__ e)
{
    extern __shared__ float sm[];
    const int t = threadIdx.x;

    if (blockIdx.x < ATTN_BLOCKS) {
        float* Qs  = sm;                  // 1024 floats (16 x 64)
        float* KsT = sm + 1024;           // 8192 floats (K: 64k x 128j, later V: 128j x 64d)
        float* S   = sm + 9216;           // 8192 floats (16 x 512)
        float* Mj  = sm + 17408;          // 512

        const int b  = blockIdx.x >> 5;
        const int i0 = (blockIdx.x & 31) * 16;

        for (int j = t; j < NN; j += 256) Mj[j] = (float)mask[b*NN + j];
        {
            const float4* q4 = reinterpret_cast<const float4*>(g_Q + (size_t)(b*NN + i0)*DH);
            reinterpret_cast<float4*>(Qs)[t] = q4[t];
        }
        __syncthreads();

        const int tx = t & 31;
        const int ty = t >> 5;
        float4* Qs4  = reinterpret_cast<float4*>(Qs);
        float4* KsT4 = reinterpret_cast<float4*>(KsT);
        float4* S4   = reinterpret_cast<float4*>(S);

        // ---- scores over 4 j-tiles of 128 ----
        for (int jt = 0; jt < 4; jt++) {
            const int j0 = jt * 128;
            {
                const int j    = t & 127;
                const int half = t >> 7;
                const float4* K4 = reinterpret_cast<const float4*>(g_K) +
                                   (size_t)(b*NN + j0 + j) * 16;
                #pragma unroll
                for (int i2 = 0; i2 < 8; i2++) {
                    int k4 = half*8 + i2;
                    float4 v = K4[k4];
                    KsT[(k4*4+0)*128 + j] = v.x;
                    KsT[(k4*4+1)*128 + j] = v.y;
                    KsT[(k4*4+2)*128 + j] = v.z;
                    KsT[(k4*4+3)*128 + j] = v.w;
                }
            }
            __syncthreads();

            float acc[2][4];
            #pragma unroll
            for (int c = 0; c < 2; c++)
                #pragma unroll
                for (int a = 0; a < 4; a++) acc[c][a] = 0.f;

            #pragma unroll 4
            for (int k4 = 0; k4 < 16; k4++) {
                float4 q0 = Qs4[ ty    *16 + k4];
                float4 q1 = Qs4[(ty+8)*16 + k4];
                #pragma unroll
                for (int kk = 0; kk < 4; kk++) {
                    float4 kv = KsT4[(k4*4 + kk)*32 + tx];
                    float qa = reinterpret_cast<const float*>(&q0)[kk];
                    float qb = reinterpret_cast<const float*>(&q1)[kk];
                    acc[0][0] = fmaf(qa, kv.x, acc[0][0]);
                    acc[0][1] = fmaf(qa, kv.y, acc[0][1]);
                    acc[0][2] = fmaf(qa, kv.z, acc[0][2]);
                    acc[0][3] = fmaf(qa, kv.w, acc[0][3]);
                    acc[1][0] = fmaf(qb, kv.x, acc[1][0]);
                    acc[1][1] = fmaf(qb, kv.y, acc[1][1]);
                    acc[1][2] = fmaf(qb, kv.z, acc[1][2]);
                    acc[1][3] = fmaf(qb, kv.w, acc[1][3]);
                }
            }

            {
                const float mi0 = Mj[i0 + ty];
                const float mi1 = Mj[i0 + ty + 8];
                const int jb = j0 + tx*4;
                float4 s0, s1;
                s0.x = (mi0*Mj[jb+0] != 0.f) ? acc[0][0]*0.125f : -1.0e9f;
                s0.y = (mi0*Mj[jb+1] != 0.f) ? acc[0][1]*0.125f : -1.0e9f;
                s0.z = (mi0*Mj[jb+2] != 0.f) ? acc[0][2]*0.125f : -1.0e9f;
                s0.w = (mi0*Mj[jb+3] != 0.f) ? acc[0][3]*0.125f : -1.0e9f;
                s1.x = (mi1*Mj[jb+0] != 0.f) ? acc[1][0]*0.125f : -1.0e9f;
                s1.y = (mi1*Mj[jb+1] != 0.f) ? acc[1][1]*0.125f : -1.0e9f;
                s1.z = (mi1*Mj[jb+2] != 0.f) ? acc[1][2]*0.125f : -1.0e9f;
                s1.w = (mi1*Mj[jb+3] != 0.f) ? acc[1][3]*0.125f : -1.0e9f;
                S4[ ty    *128 + (jb>>2)] = s0;
                S4[(ty+8)*128 + (jb>>2)] = s1;
            }
            __syncthreads();
        }

        // ---- softmax: warp per row pair ----
        {
            const int warp = t >> 5, lane = t & 31;
            #pragma unroll
            for (int rr = 0; rr < 2; rr++) {
                int row = warp*2 + rr;
                float vals[16];
                float mx = -3.4e38f;
                #pragma unroll
                for (int m = 0; m < 16; m++) {
                    vals[m] = S[row*NN + lane + 32*m];
                    mx = fmaxf(mx, vals[m]);
                }
                #pragma unroll
                for (int o = 16; o > 0; o >>= 1)
                    mx = fmaxf(mx, __shfl_xor_sync(0xffffffffu, mx, o));
                float sum = 0.f;
                #pragma unroll
                for (int m = 0; m < 16; m++) { vals[m] = __expf(vals[m] - mx); sum += vals[m]; }
                #pragma unroll
                for (int o = 16; o > 0; o >>= 1)
                    sum += __shfl_xor_sync(0xffffffffu, sum, o);
                float inv = 1.f / sum;
                #pragma unroll
                for (int m = 0; m < 16; m++) S[row*NN + lane + 32*m] = vals[m]*inv;
            }
        }
        __syncthreads();

        // ---- out = P @ V, V staged through smem in 4 j-tiles ----
        {
            const int ty4 = t >> 4;       // row 0..15
            const int tx4 = t & 15;       // dd group
            float4 acc = {0.f, 0.f, 0.f, 0.f};
            float* Vs  = KsT;             // reuse: 128 x 64
            float4* Vs4 = reinterpret_cast<float4*>(Vs);
            const float4* __restrict__ V4 =
                reinterpret_cast<const float4*>(g_V) + (size_t)b*NN*16;

            for (int jt = 0; jt < 4; jt++) {
                const int j0 = jt * 128;
                #pragma unroll
                for (int i2 = 0; i2 < 8; i2++) {
                    int idx = t + i2*256;             // 0..2047
                    int row = idx >> 4, c4 = idx & 15;
                    Vs4[row*16 + c4] = V4[(size_t)(j0 + row)*16 + c4];
                }
                __syncthreads();

                #pragma unroll 4
                for (int j4 = 0; j4 < 32; j4++) {
                    float4 s  = S4[ty4*128 + jt*32 + j4];
                    float4 v0 = Vs4[(j4*4+0)*16 + tx4];
                    float4 v1 = Vs4[(j4*4+1)*16 + tx4];
                    float4 v2 = Vs4[(j4*4+2)*16 + tx4];
                    float4 v3 = Vs4[(j4*4+3)*16 + tx4];
                    acc.x = fmaf(s.x, v0.x, acc.x); acc.y = fmaf(s.x, v0.y, acc.y);
                    acc.z = fmaf(s.x, v0.z, acc.z); acc.w = fmaf(s.x, v0.w, acc.w);
                    acc.x = fmaf(s.y, v1.x, acc.x); acc.y = fmaf(s.y, v1.y, acc.y);
                    acc.z = fmaf(s.y, v1.z, acc.z); acc.w = fmaf(s.y, v1.w, acc.w);
                    acc.x = fmaf(s.z, v2.x, acc.x); acc.y = fmaf(s.z, v2.y, acc.y);
                    acc.z = fmaf(s.z, v2.z, acc.z); acc.w = fmaf(s.z, v2.w, acc.w);
                    acc.x = fmaf(s.w, v3.x, acc.x); acc.y = fmaf(s.w, v3.y, acc.y);
                    acc.z = fmaf(s.w, v3.z, acc.z); acc.w = fmaf(s.w, v3.w, acc.w);
                }
                __syncthreads();
            }

            float m = Mj[i0 + ty4];
            acc.x *= m; acc.y *= m; acc.z *= m; acc.w *= m;
            reinterpret_cast<float4*>(out)[(size_t)(b*NN + i0 + ty4)*16 + tx4] = acc;
        }
    }

    // -------- copy phase: every warp work-steals 32KB chunks --------
    {
        const int lane = t & 31;
        const float4* __restrict__ src = reinterpret_cast<const float4*>(e);
        float4* __restrict__ dst = reinterpret_cast<float4*>(out + (size_t)NROWS*DH);

        for (;;) {
            int c = 0;
            if (lane == 0) c = atomicAdd(&g_chunk, 1);
            c = __shfl_sync(0xffffffffu, c, 0);
            if (c >= NCHUNKS) break;

            const size_t base = (size_t)c * CHUNK4 + lane;   // 2048 float4 per chunk
            #pragma unroll 1
            for (int u = 0; u < 64; u += 8) {                // 64 float4/lane, 8-deep
                float4 r[8];
                #pragma unroll
                for (int v = 0; v < 8; v++)
                    r[v] = __ldcs(&src[base + (size_t)(u+v)*32]);
                #pragma unroll
                for (int v = 0; v < 8; v++)
                    __stcs(&dst[base + (size_t)(u+v)*32], r[v]);
            }
        }
    }
}

// ---------------------------------------------------------------------------
extern "C" void kernel_launch(void* const* d_in, const int* in_sizes, int n_in,
                              void* d_out, int out_size)
{
    const float* x  = (const float*)d_in[0];
    const float* e  = (const float*)d_in[1];
    const int*  msk = (const int*)  d_in[2];
    const float* Wq = (const float*)d_in[3];
    const float* bq = (const float*)d_in[4];
    const float* Wk = (const float*)d_in[5];
    const float* bk = (const float*)d_in[6];
    const float* Wv = (const float*)d_in[7];
    const float* bv = (const float*)d_in[8];
    float* out = (float*)d_out;

    qkv_kernel<<<128, 256>>>(x, msk, Wq, bq, Wk, bk, Wv, bv);

    cudaFuncSetAttribute(fused_kernel, cudaFuncAttributeMaxDynamicSharedMemorySize,
                         SMEM_BYTES);
    fused_kernel<<<GRID_TOTAL, 256, SMEM_BYTES>>>(msk, out, e);
}